// round 15
// baseline (speedup 1.0000x reference)
#include <cuda_runtime.h>

#define BATCH 16
#define NL 3
#define NBL (BATCH * NL)
#define NBINS 1152
#define CAP 4096
#define SBUF 512
#define ND 1000
#define NALL (NL * ND)
#define CHUNK 16384
#define SPAD(i) ((i) + ((i) >> 3))   // bank-conflict padding for u64 shared arrays

// grid layout (per-layer chunk counts) — R9/R11 proven config
#define BPI0 80
#define BPI1 20
#define BPI2 5
#define BLK0 (BATCH * BPI0)              // 1280
#define BLK01 (BLK0 + BATCH * BPI1)      // 1600
#define BLKALL (BLK01 + BATCH * BPI2)    // 1680

// ---------------- persistent scratch (zero at load; self-resetting each replay) -------
__device__ unsigned int       g_cnt[NBL];     // reset by each bl's sorter
__device__ unsigned int       g_arr[NBL];     // per-bl arrival counter; reset by sorter
__device__ unsigned int       g_batch[BATCH]; // per-batch arrival counter; reset by merger
__device__ unsigned long long g_cand[NBL][CAP];
__device__ float              g_det[BATCH][NL][ND][7];

__constant__ float c_thr[3] = {1.0f - 3000.0f / 1310720.0f,
                               1.0f - 3000.0f / 327680.0f,
                               1.0f - 1500.0f / 81920.0f};
__constant__ int   c_K[3]     = {2000, 2000, 1024};
__constant__ int   c_shift[3] = {6, 8, 9};

__device__ __forceinline__ int bin_of(unsigned int bits) {
    if (bits >= 0x3F800000u) return 1150;
    if (bits >= 0x3F000000u) return 126 + (int)((bits - 0x3F000000u) >> 13);
    return (int)(bits >> 23);
}

__device__ __forceinline__ unsigned int sel_bin(unsigned long long key, int shift) {
    unsigned int bits = (unsigned int)(key >> 32);
    int off = (int)(0x3F800000u - bits);
    return (off <= 0) ? 0u : (unsigned int)min(1023, off >> shift);
}

__device__ __forceinline__ void ce(unsigned long long& a, unsigned long long& b, bool dir) {
    if ((a < b) == dir) { unsigned long long t = a; a = b; b = t; }
}

// smem bitonic, descending, n=2048, 256 threads, padded indexing
__device__ void bitonic_smem(unsigned long long* s, int n, int tid) {
    for (int t8 = tid; t8 < (n >> 3); t8 += 256) {
        int g = t8 << 3;
        unsigned long long v[8];
#pragma unroll
        for (int x = 0; x < 8; x++) v[x] = s[SPAD(g + x)];
        ce(v[0], v[1], true);  ce(v[2], v[3], false);
        ce(v[4], v[5], true);  ce(v[6], v[7], false);
        ce(v[0], v[2], true);  ce(v[1], v[3], true);
        ce(v[4], v[6], false); ce(v[5], v[7], false);
        ce(v[0], v[1], true);  ce(v[2], v[3], true);
        ce(v[4], v[5], false); ce(v[6], v[7], false);
        bool d8 = ((g & 8) == 0);
        ce(v[0], v[4], d8); ce(v[1], v[5], d8); ce(v[2], v[6], d8); ce(v[3], v[7], d8);
        ce(v[0], v[2], d8); ce(v[1], v[3], d8); ce(v[4], v[6], d8); ce(v[5], v[7], d8);
        ce(v[0], v[1], d8); ce(v[2], v[3], d8); ce(v[4], v[5], d8); ce(v[6], v[7], d8);
#pragma unroll
        for (int x = 0; x < 8; x++) s[SPAD(g + x)] = v[x];
    }
    __syncthreads();
    for (int k = 16; k <= n; k <<= 1) {
        for (int j = k >> 1; j >= 8; j >>= 1) {
            for (int idx = tid; idx < (n >> 1); idx += 256) {
                int i = ((idx & ~(j - 1)) << 1) | (idx & (j - 1));
                int p = i + j;
                bool dir = ((i & k) == 0);
                unsigned long long a = s[SPAD(i)], b = s[SPAD(p)];
                if ((a < b) == dir) { s[SPAD(i)] = b; s[SPAD(p)] = a; }
            }
            __syncthreads();
        }
        for (int t8 = tid; t8 < (n >> 3); t8 += 256) {
            int g = t8 << 3;
            bool dir = ((g & k) == 0);
            unsigned long long v[8];
#pragma unroll
            for (int x = 0; x < 8; x++) v[x] = s[SPAD(g + x)];
            ce(v[0], v[4], dir); ce(v[1], v[5], dir); ce(v[2], v[6], dir); ce(v[3], v[7], dir);
            ce(v[0], v[2], dir); ce(v[1], v[3], dir); ce(v[4], v[6], dir); ce(v[5], v[7], dir);
            ce(v[0], v[1], dir); ce(v[2], v[3], dir); ce(v[4], v[5], dir); ce(v[6], v[7], dir);
#pragma unroll
            for (int x = 0; x < 8; x++) s[SPAD(g + x)] = v[x];
        }
        __syncthreads();
    }
}

// global-memory bitonic (exactness backstop; essentially never taken)
__device__ void bitonic_global(unsigned long long* g, int n, int tid) {
    for (int k = 2; k <= n; k <<= 1)
        for (int j = k >> 1; j > 0; j >>= 1) {
            for (int idx = tid; idx < (n >> 1); idx += 256) {
                int i = ((idx & ~(j - 1)) << 1) | (idx & (j - 1));
                int p = i + j;
                bool dir = ((i & k) == 0);
                unsigned long long a = g[i], b = g[p];
                if ((a < b) == dir) { g[i] = b; g[p] = a; }
            }
            __syncthreads();
        }
}

// ============================ the single fused kernel ================================
__global__ void __launch_bounds__(256, 8)
fused_kernel(const float* __restrict__ h0, const float* __restrict__ h1,
             const float* __restrict__ h2,
             const float* __restrict__ tl0, const float* __restrict__ br0,
             const float* __restrict__ tl1, const float* __restrict__ br1,
             const float* __restrict__ tl2, const float* __restrict__ br2,
             float* __restrict__ out) {
    __shared__ unsigned long long sA[SPAD(2048)];   // collect staging / sort buf / merge scores
    __shared__ unsigned int sh_hist[NBINS];
    __shared__ unsigned char sh_flag[2048];
    __shared__ unsigned int sh_u[8];
    __shared__ unsigned int sh_cnt, sh_base, sh_cut, sh_total, sh_scnt, sh_tb;
    __shared__ int sh_sorter, sh_last;

    int tid = threadIdx.x, lane = tid & 31, warp = tid >> 5;

    // ---------------- collect phase ----------------
    int bid = blockIdx.x, layer, img, chunk, n, bpi;
    const float* heat;
    if (bid < BLK0)       { layer = 0; int r = bid;         img = r / BPI0; chunk = r - img * BPI0; n = 80 * 16384; heat = h0; bpi = BPI0; }
    else if (bid < BLK01) { layer = 1; int r = bid - BLK0;  img = r / BPI1; chunk = r - img * BPI1; n = 80 * 4096;  heat = h1; bpi = BPI1; }
    else                  { layer = 2; int r = bid - BLK01; img = r / BPI2; chunk = r - img * BPI2; n = 80 * 1024;  heat = h2; bpi = BPI2; }
    int bl = img * NL + layer;
    float thr = c_thr[layer];
    unsigned int tb = __float_as_uint(thr);

    unsigned long long* s_buf = sA;
    if (tid == 0) sh_cnt = 0u;
    __syncthreads();

    const float4* p = reinterpret_cast<const float4*>(heat + (size_t)img * n) + chunk * (CHUNK / 4);
    unsigned int base_idx = (unsigned int)chunk * CHUNK;

#pragma unroll
    for (int it = 0; it < 4; it++) {
        int i0 = it * 1024 + tid;
        float4 v[4];
#pragma unroll
        for (int u = 0; u < 4; u++) v[u] = p[i0 + u * 256];
        float mx = 0.0f;
#pragma unroll
        for (int u = 0; u < 4; u++)
            mx = fmaxf(mx, fmaxf(fmaxf(v[u].x, v[u].y), fmaxf(v[u].z, v[u].w)));
        if (mx >= thr) {
#pragma unroll
            for (int u = 0; u < 4; u++) {
                unsigned int fi = base_idx + 4u * (unsigned int)(i0 + u * 256);
                float vv[4] = {v[u].x, v[u].y, v[u].z, v[u].w};
#pragma unroll
                for (int c = 0; c < 4; c++) {
                    unsigned int bits = __float_as_uint(vv[c]);
                    if (bits >= tb) {
                        unsigned int pos = atomicAdd(&sh_cnt, 1u);
                        if (pos < SBUF)
                            s_buf[pos] = ((unsigned long long)bits << 32)
                                       | (unsigned int)(~(fi + (unsigned int)c));
                    }
                }
            }
        }
    }
    __syncthreads();

    unsigned int cnt0 = sh_cnt;
    if (cnt0) {
        if (tid == 0)
            sh_base = atomicAdd(&g_cnt[bl], (cnt0 > SBUF) ? (CAP + 1u) : cnt0);
        __syncthreads();
        if (cnt0 <= SBUF) {
            unsigned int base = sh_base;
            for (unsigned int i = tid; i < cnt0; i += 256) {
                unsigned int g = base + i;
                if (g < CAP) g_cand[bl][g] = s_buf[i];
            }
        }
    }

    // release + arrive (canonical threadfence-reduction pattern)
    __threadfence();
    __syncthreads();
    if (tid == 0) {
        unsigned int prev = atomicAdd(&g_arr[bl], 1u);
        sh_sorter = (prev == (unsigned int)(bpi - 1));
    }
    __syncthreads();
    if (!sh_sorter) return;
    __threadfence();   // acquire peers' g_cand/g_cnt writes

    // ---------------- sorter phase (one block per (b,layer)) ----------------
    int hwv, logW;
    float scale;
    const float *tlg, *brg;
    if (layer == 0)      { hwv = 16384; logW = 7; scale = 8.0f;  tlg = tl0; brg = br0; }
    else if (layer == 1) { hwv = 4096;  logW = 6; scale = 16.0f; tlg = tl1; brg = br1; }
    else                 { hwv = 1024;  logW = 5; scale = 32.0f; tlg = tl2; brg = br2; }
    int b = img;
    int K = c_K[layer], shift = c_shift[layer];
    int n_layer = 80 * hwv;

    unsigned int cnt = g_cnt[bl];
    if (cnt < (unsigned int)K || cnt > CAP) {
        // -------- exact fallback rebuild (rare) --------
        for (int i = tid; i < NBINS; i += 256) sh_hist[i] = 0u;
        __syncthreads();
        const float4* pp = reinterpret_cast<const float4*>(heat + (size_t)b * n_layer);
        int n4 = n_layer >> 2;
        for (int i = tid; i < n4; i += 256) {
            float4 v = pp[i];
            atomicAdd(&sh_hist[bin_of(__float_as_uint(v.x))], 1u);
            atomicAdd(&sh_hist[bin_of(__float_as_uint(v.y))], 1u);
            atomicAdd(&sh_hist[bin_of(__float_as_uint(v.z))], 1u);
            atomicAdd(&sh_hist[bin_of(__float_as_uint(v.w))], 1u);
        }
        __syncthreads();
        if (tid == 0) {
            int bidx = NBINS - 1;
            unsigned int cum = 0;
            while (true) {
                cum += sh_hist[bidx];
                if (cum >= (unsigned int)K || bidx == 0) break;
                --bidx;
            }
            unsigned int lb;
            if (bidx >= 1150)     lb = 0x3F800000u;
            else if (bidx >= 126) lb = 0x3F000000u + ((unsigned int)(bidx - 126) << 13);
            else                  lb = ((unsigned int)bidx) << 23;
            sh_tb = lb;
            g_cnt[bl] = 0u;
        }
        __syncthreads();
        unsigned int tb2 = sh_tb;
        for (int i = tid; i < n4; i += 256) {
            float4 v = pp[i];
            unsigned int fi = 4u * (unsigned int)i;
            float vv[4] = {v.x, v.y, v.z, v.w};
#pragma unroll
            for (int c = 0; c < 4; c++) {
                unsigned int bits = __float_as_uint(vv[c]);
                if (bits >= tb2) {
                    unsigned int pos = atomicAdd(&g_cnt[bl], 1u);
                    if (pos < CAP)
                        g_cand[bl][pos] = ((unsigned long long)bits << 32)
                                        | (unsigned int)(~(fi + (unsigned int)c));
                }
            }
        }
        __syncthreads();
        cnt = g_cnt[bl];
    }
    int m = (cnt > (unsigned int)CAP) ? CAP : (int)cnt;

    if (m <= 2048) {
        for (int i = tid; i < 2048; i += 256)
            sA[SPAD(i)] = (i < m) ? g_cand[bl][i] : 0ull;
        __syncthreads();
        bitonic_smem(sA, 2048, tid);
    } else {
        // histogram pre-selection to <= 2048 keys (superset of exact top-K)
        for (int i = tid; i < 1024; i += 256) sh_hist[i] = 0u;
        __syncthreads();
        for (int i = tid; i < m; i += 256)
            atomicAdd(&sh_hist[sel_bin(g_cand[bl][i], shift)], 1u);
        __syncthreads();
        if (tid < 32) {
            unsigned int seg = 0;
            for (int j = 0; j < 32; j++) seg += sh_hist[(tid << 5) + j];
            unsigned int incl = seg;
#pragma unroll
            for (int off = 1; off < 32; off <<= 1) {
                unsigned int t = __shfl_up_sync(0xffffffffu, incl, off);
                if (lane >= off) incl += t;
            }
            unsigned int ex = incl - seg;
            if (ex < (unsigned int)K && incl >= (unsigned int)K) {
                unsigned int cum = ex;
                int bb = tid << 5;
                while (cum + sh_hist[bb] < (unsigned int)K) { cum += sh_hist[bb]; bb++; }
                sh_cut = (unsigned int)bb;
                sh_total = cum + sh_hist[bb];
            }
        }
        if (tid == 0) sh_scnt = 0u;
        __syncthreads();
        unsigned int cut = sh_cut, total = sh_total;
        if (total <= 2048u) {
            for (int i = tid; i < m; i += 256) {
                unsigned long long key = g_cand[bl][i];
                if (sel_bin(key, shift) <= cut) {
                    unsigned int pos = atomicAdd(&sh_scnt, 1u);
                    sA[SPAD(pos)] = key;
                }
            }
            __syncthreads();
            for (unsigned int i = total + tid; i < 2048u; i += 256u) sA[SPAD(i)] = 0ull;
            __syncthreads();
            bitonic_smem(sA, 2048, tid);
        } else {
            // backstop: sort all m in global, then take top 2048
            for (int i = m + tid; i < CAP; i += 256) g_cand[bl][i] = 0ull;
            __syncthreads();
            bitonic_global(g_cand[bl], CAP, tid);
            for (int i = tid; i < 2048; i += 256) sA[SPAD(i)] = g_cand[bl][i];
            __syncthreads();
        }
    }
    // sA[SPAD(0..K-1)] = exact sorted top-K: value desc, index asc on ties.

    // ---------------- decode: flags pass, scan, selective re-decode ----------------
    const float* tlp = tlg + (size_t)b * 2 * hwv;
    const float* brp = brg + (size_t)b * 2 * hwv;
    int Wm1 = (1 << logW) - 1;
    int base_r = tid * 8;
    int tsum = 0;
#pragma unroll
    for (int u = 0; u < 8; u++) {
        int r = base_r + u;
        int f = 0;
        if (r < K) {
            unsigned long long key = sA[SPAD(r)];
            unsigned int idx = ~(unsigned int)key;
            int sp = (int)(idx & (unsigned int)(hwv - 1));
            float fy = (float)(sp >> logW);
            float fx = (float)(sp & Wm1);
            float tx = tlp[sp], ty = tlp[hwv + sp];
            float bx = brp[sp], by = brp[hwv + sp];
            float tlx = fx - fmaf(1.5f, tx, 2.25f);
            float tly = fy - fmaf(1.5f, ty, 2.25f);
            float brx = fx + fmaf(1.5f, bx, 2.25f);
            float bry = fy + fmaf(1.5f, by, 2.25f);
            f = (!((brx < tlx) || (bry < tly))) ? 1 : 0;
        }
        sh_flag[base_r + u] = (unsigned char)f;
        tsum += f;
    }
    int incl2 = tsum;
#pragma unroll
    for (int off = 1; off < 32; off <<= 1) {
        int t2 = __shfl_up_sync(0xffffffffu, incl2, off);
        if (lane >= off) incl2 += t2;
    }
    if (lane == 31) sh_u[warp] = (unsigned int)incl2;
    __syncthreads();
    if (tid < 8) {
        unsigned int v = sh_u[tid];
#pragma unroll
        for (int off = 1; off < 8; off <<= 1) {
            unsigned int t2 = __shfl_up_sync(0xffu, v, off);
            if (tid >= off) v += t2;
        }
        sh_u[tid] = v;
    }
    __syncthreads();
    int total_valid = (int)sh_u[7];
    int run = (warp ? (int)sh_u[warp - 1] : 0) + (incl2 - tsum);
#pragma unroll
    for (int u = 0; u < 8; u++) {
        int r = base_r + u;
        if (r < K) {
            int f = (int)sh_flag[r];
            int pos = f ? run : (total_valid + (r - run));
            run += f;
            if (pos < ND) {
                unsigned long long key = sA[SPAD(r)];
                unsigned int bits = (unsigned int)(key >> 32);
                unsigned int idx = ~(unsigned int)key;
                int sp = (int)(idx & (unsigned int)(hwv - 1));
                float fy = (float)(sp >> logW);
                float fx = (float)(sp & Wm1);
                float tx = tlp[sp], ty = tlp[hwv + sp];
                float bx = brp[sp], by = brp[hwv + sp];
                float tlx = fx - fmaf(1.5f, tx, 2.25f);
                float tly = fy - fmaf(1.5f, ty, 2.25f);
                float brx = fx + fmaf(1.5f, bx, 2.25f);
                float bry = fy + fmaf(1.5f, by, 2.25f);
                float* d = g_det[b][layer][pos];
                d[0] = f ? __uint_as_float(bits) : -1.0f;
                d[1] = tlx * scale; d[2] = tly * scale;
                d[3] = brx * scale; d[4] = bry * scale;
                d[5] = 0.0f; d[6] = 0.0f;
            }
        }
    }
    __syncthreads();
    if (tid < 7) g_det[b][layer][6][tid] = (float)layer;   // det.at[:,6,:] = layer
    if (tid == 0) { g_cnt[bl] = 0u; g_arr[bl] = 0u; }      // reset for next replay

    // ---------------- fused final merge: third sorter of batch b does it --------------
    __threadfence();
    __syncthreads();
    if (tid == 0) {
        unsigned int prev = atomicAdd(&g_batch[b], 1u);
        sh_last = (prev == 2u);
    }
    __syncthreads();
    if (!sh_last) return;
    __threadfence();

    unsigned int* scores = (unsigned int*)sA;   // 3000 u32 = 12 KB <= 18.4 KB
    for (int i = tid; i < NALL; i += 256) {
        int l = i / ND, r = i - l * ND;
        unsigned int sb = __float_as_uint(g_det[b][l][r][0]);
        scores[i] = (sb & 0x80000000u) ? ~sb : (sb | 0x80000000u);  // monotone map
    }
    __syncthreads();

    for (int e = tid; e < NALL; e += 256) {
        unsigned int my = scores[e];
        int rank = 0;
#pragma unroll
        for (int l = 0; l < NL; l++) {
            int basei = l * ND;
            // holed (999-elem) descending list; compound key (score desc, element-id asc)
            int lo = 0, hi = ND - 1;
            while (lo < hi) {
                int mid = (lo + hi) >> 1;
                int j = basei + mid + (mid >= 6);
                unsigned int sj = scores[j];
                bool gtr = (sj > my) || (sj == my && j < e);
                if (gtr) lo = mid + 1; else hi = mid;
            }
            rank += lo;
            int ovj = basei + 6;
            unsigned int so = scores[ovj];
            rank += ((so > my) || (so == my && ovj < e)) ? 1 : 0;
        }
        if (rank < ND) {
            int l = e / ND, r = e - l * ND;
            const float* src = g_det[b][l][r];
            float* dst = out + ((size_t)b * ND + rank) * 7;
#pragma unroll
            for (int c = 0; c < 7; c++) dst[c] = src[c];
        }
    }
    __syncthreads();
    if (tid == 0) g_batch[b] = 0u;                         // reset for next replay
}

extern "C" void kernel_launch(void* const* d_in, const int* in_sizes, int n_in,
                              void* d_out, int out_size) {
    const int hw[3] = {16384, 4096, 1024};

    // Resolve inputs BY SIZE (metadata order is heat0, tl0, br0, heat1, ...).
    const float* heat[3] = {0, 0, 0};
    const float* tl[3]   = {0, 0, 0};
    const float* br[3]   = {0, 0, 0};
    for (int i = 0; i < n_in; i++) {
        long long sz = in_sizes[i];
        for (int l = 0; l < 3; l++) {
            if (sz == (long long)BATCH * 80 * hw[l]) {
                heat[l] = (const float*)d_in[i];
            } else if (sz == (long long)BATCH * 2 * hw[l]) {
                if (!tl[l]) tl[l] = (const float*)d_in[i];
                else        br[l] = (const float*)d_in[i];
            }
        }
    }

    fused_kernel<<<BLKALL, 256>>>(heat[0], heat[1], heat[2],
                                  tl[0], br[0], tl[1], br[1], tl[2], br[2],
                                  (float*)d_out);
}

// round 16
// speedup vs baseline: 3.0843x; 3.0843x over previous
#include <cuda_runtime.h>

#define BATCH 16
#define NL 3
#define NBL (BATCH * NL)
#define NBINS 1152
#define CAP 4096
#define SBUF 512
#define ND 1000
#define NALL (NL * ND)
#define CHUNK 16384
#define SPAD(i) ((i) + ((i) >> 3))   // bank-conflict padding for u64 shared arrays

// grid layout for collectA (per-layer chunk counts) — R9/R11 proven config
#define BPI0 80
#define BPI1 20
#define BPI2 5
#define BLK0 (BATCH * BPI0)              // 1280
#define BLK01 (BLK0 + BATCH * BPI1)      // 1600
#define BLKALL (BLK01 + BATCH * BPI2)    // 1680

// ---------------- persistent scratch (zero at load; self-resetting each replay) -------
__device__ unsigned int       g_cnt[NBL];     // zeroed by sortdet at end of each replay
__device__ unsigned int       g_batch[BATCH]; // per-batch arrival counter; reset by merger
__device__ unsigned long long g_cand[NBL][CAP];
__device__ float              g_det[BATCH][NL][ND][7];

__constant__ float c_thr[3] = {1.0f - 3000.0f / 1310720.0f,
                               1.0f - 3000.0f / 327680.0f,
                               1.0f - 1500.0f / 81920.0f};
__constant__ int   c_K[3]      = {2000, 2000, 1024};
__constant__ int   c_shift[3]  = {6, 8, 9};   // selection histogram bin shift per layer

// Monotone bin mapping (fallback path only): fine bins over [0.5,1).
__device__ __forceinline__ int bin_of(unsigned int bits) {
    if (bits >= 0x3F800000u) return 1150;
    if (bits >= 0x3F000000u) return 126 + (int)((bits - 0x3F000000u) >> 13);
    return (int)(bits >> 23);
}

__device__ __forceinline__ unsigned int sel_bin(unsigned long long key, int shift) {
    unsigned int bits = (unsigned int)(key >> 32);
    int off = (int)(0x3F800000u - bits);
    return (off <= 0) ? 0u : (unsigned int)min(1023, off >> shift);
}

// ---------------- pass 1: single-pass collect with static thresholds (R9) -------------
__global__ void __launch_bounds__(256, 8) collectA_kernel(const float* __restrict__ h0,
                                                          const float* __restrict__ h1,
                                                          const float* __restrict__ h2) {
    __shared__ unsigned long long s_buf[SBUF];
    __shared__ unsigned int s_cnt;
    __shared__ unsigned int s_base;

    int bid = blockIdx.x, layer, img, chunk, n;
    const float* heat;
    if (bid < BLK0)       { layer = 0; int r = bid;         img = r / BPI0; chunk = r - img * BPI0; n = 80 * 16384; heat = h0; }
    else if (bid < BLK01) { layer = 1; int r = bid - BLK0;  img = r / BPI1; chunk = r - img * BPI1; n = 80 * 4096;  heat = h1; }
    else                  { layer = 2; int r = bid - BLK01; img = r / BPI2; chunk = r - img * BPI2; n = 80 * 1024;  heat = h2; }
    int bl = img * NL + layer;
    float thr = c_thr[layer];
    unsigned int tb = __float_as_uint(thr);

    int tid = threadIdx.x;
    if (tid == 0) s_cnt = 0u;
    __syncthreads();

    const float4* p = reinterpret_cast<const float4*>(heat + (size_t)img * n) + chunk * (CHUNK / 4);
    unsigned int base_idx = (unsigned int)chunk * CHUNK;

#pragma unroll
    for (int it = 0; it < 4; it++) {
        int i0 = it * 1024 + tid;
        float4 v[4];
#pragma unroll
        for (int u = 0; u < 4; u++) v[u] = p[i0 + u * 256];   // batched independent loads
        float mx = 0.0f;
#pragma unroll
        for (int u = 0; u < 4; u++)
            mx = fmaxf(mx, fmaxf(fmaxf(v[u].x, v[u].y), fmaxf(v[u].z, v[u].w)));
        if (mx >= thr) {   // rare (~1% of threads)
#pragma unroll
            for (int u = 0; u < 4; u++) {
                unsigned int fi = base_idx + 4u * (unsigned int)(i0 + u * 256);
                float vv[4] = {v[u].x, v[u].y, v[u].z, v[u].w};
#pragma unroll
                for (int c = 0; c < 4; c++) {
                    unsigned int bits = __float_as_uint(vv[c]);
                    if (bits >= tb) {
                        unsigned int pos = atomicAdd(&s_cnt, 1u);
                        if (pos < SBUF)
                            s_buf[pos] = ((unsigned long long)bits << 32)
                                       | (unsigned int)(~(fi + (unsigned int)c));
                    }
                }
            }
        }
    }
    __syncthreads();

    unsigned int cnt = s_cnt;
    if (cnt == 0u) return;
    if (tid == 0) {
        s_base = atomicAdd(&g_cnt[bl], (cnt > SBUF) ? (CAP + 1u) : cnt);
    }
    __syncthreads();
    if (cnt > SBUF) return;

    unsigned int base = s_base;
    for (unsigned int i = tid; i < cnt; i += 256) {
        unsigned int g = base + i;
        if (g < CAP) g_cand[bl][g] = s_buf[i];
    }
}

// ---------------- register-blocked, padded bitonic sort (descending), NT threads ------
__device__ __forceinline__ void ce(unsigned long long& a, unsigned long long& b, bool dir) {
    if ((a < b) == dir) { unsigned long long t = a; a = b; b = t; }
}

template <int NT>
__device__ void bitonic_desc_opt(unsigned long long* s, int n, int tid) {
    for (int t8 = tid; t8 < (n >> 3); t8 += NT) {
        int g = t8 << 3;
        unsigned long long v[8];
#pragma unroll
        for (int x = 0; x < 8; x++) v[x] = s[SPAD(g + x)];
        ce(v[0], v[1], true);  ce(v[2], v[3], false);
        ce(v[4], v[5], true);  ce(v[6], v[7], false);
        ce(v[0], v[2], true);  ce(v[1], v[3], true);
        ce(v[4], v[6], false); ce(v[5], v[7], false);
        ce(v[0], v[1], true);  ce(v[2], v[3], true);
        ce(v[4], v[5], false); ce(v[6], v[7], false);
        bool d8 = ((g & 8) == 0);
        ce(v[0], v[4], d8); ce(v[1], v[5], d8); ce(v[2], v[6], d8); ce(v[3], v[7], d8);
        ce(v[0], v[2], d8); ce(v[1], v[3], d8); ce(v[4], v[6], d8); ce(v[5], v[7], d8);
        ce(v[0], v[1], d8); ce(v[2], v[3], d8); ce(v[4], v[5], d8); ce(v[6], v[7], d8);
#pragma unroll
        for (int x = 0; x < 8; x++) s[SPAD(g + x)] = v[x];
    }
    __syncthreads();

    for (int k = 16; k <= n; k <<= 1) {
        for (int j = k >> 1; j >= 8; j >>= 1) {
            for (int idx = tid; idx < (n >> 1); idx += NT) {
                int i = ((idx & ~(j - 1)) << 1) | (idx & (j - 1));
                int p = i + j;
                bool dir = ((i & k) == 0);
                unsigned long long a = s[SPAD(i)], b = s[SPAD(p)];
                if ((a < b) == dir) { s[SPAD(i)] = b; s[SPAD(p)] = a; }
            }
            __syncthreads();
        }
        for (int t8 = tid; t8 < (n >> 3); t8 += NT) {
            int g = t8 << 3;
            bool dir = ((g & k) == 0);
            unsigned long long v[8];
#pragma unroll
            for (int x = 0; x < 8; x++) v[x] = s[SPAD(g + x)];
            ce(v[0], v[4], dir); ce(v[1], v[5], dir); ce(v[2], v[6], dir); ce(v[3], v[7], dir);
            ce(v[0], v[2], dir); ce(v[1], v[3], dir); ce(v[4], v[6], dir); ce(v[5], v[7], dir);
            ce(v[0], v[1], dir); ce(v[2], v[3], dir); ce(v[4], v[5], dir); ce(v[6], v[7], dir);
#pragma unroll
            for (int x = 0; x < 8; x++) s[SPAD(g + x)] = v[x];
        }
        __syncthreads();
    }
}

// ---- pass 2: (fallback) + top-2048 selection + sort + decode + FUSED final merge -----
// launch_bounds(1024, 1): only 48 blocks ever run (1/SM), so give ptxas the full
// 64-reg budget to avoid local-memory spills in the register-blocked bitonic.
__global__ void __launch_bounds__(1024, 1) sortdet_kernel(const float* __restrict__ h0,
                                                          const float* __restrict__ h1,
                                                          const float* __restrict__ h2,
                                                          const float* __restrict__ tl0,
                                                          const float* __restrict__ br0,
                                                          const float* __restrict__ tl1,
                                                          const float* __restrict__ br1,
                                                          const float* __restrict__ tl2,
                                                          const float* __restrict__ br2,
                                                          float* __restrict__ out) {
    __shared__ unsigned long long s[SPAD(CAP)];  // sort buffer; reused as merge key array
    __shared__ unsigned int sh_hist[NBINS];      // fallback hist / selection hist
    __shared__ unsigned int sh_wscan[32];
    __shared__ unsigned int sh_tb, sh_scnt, sh_cut, sh_total;
    __shared__ int wsum[32];
    __shared__ int wtot;
    __shared__ int sh_last;
    __shared__ unsigned long long ovk[NL];

    int bl = blockIdx.x, tid = threadIdx.x;
    int b = bl / NL, layer = bl % NL;
    int lane = tid & 31, warp = tid >> 5;

    const int   hws[3]   = {16384, 4096, 1024};
    const int   logWs[3] = {7, 6, 5};
    const float scs[3]   = {8.0f, 16.0f, 32.0f};
    int hw = hws[layer], logW = logWs[layer], K = c_K[layer];
    float scale = scs[layer];
    const float* heat = (layer == 0) ? h0 : (layer == 1) ? h1 : h2;
    const float* tl   = (layer == 0) ? tl0 : (layer == 1) ? tl1 : tl2;
    const float* br   = (layer == 0) ? br0 : (layer == 1) ? br1 : br2;
    int n_layer = 80 * hw;

    unsigned int cnt = g_cnt[bl];
    if (cnt < (unsigned int)K || cnt > CAP) {
        // -------- exact fallback, fully within this block --------
        for (int i = tid; i < NBINS; i += 1024) sh_hist[i] = 0u;
        __syncthreads();
        const float4* p = reinterpret_cast<const float4*>(heat + (size_t)b * n_layer);
        int n4 = n_layer >> 2;
        for (int i = tid; i < n4; i += 1024) {
            float4 v = p[i];
            atomicAdd(&sh_hist[bin_of(__float_as_uint(v.x))], 1u);
            atomicAdd(&sh_hist[bin_of(__float_as_uint(v.y))], 1u);
            atomicAdd(&sh_hist[bin_of(__float_as_uint(v.z))], 1u);
            atomicAdd(&sh_hist[bin_of(__float_as_uint(v.w))], 1u);
        }
        __syncthreads();
        if (tid == 0) {
            int bidx = NBINS - 1;
            unsigned int cum = 0;
            while (true) {
                cum += sh_hist[bidx];
                if (cum >= (unsigned int)K || bidx == 0) break;
                --bidx;
            }
            unsigned int lb;
            if (bidx >= 1150)     lb = 0x3F800000u;
            else if (bidx >= 126) lb = 0x3F000000u + ((unsigned int)(bidx - 126) << 13);
            else                  lb = ((unsigned int)bidx) << 23;
            sh_tb = lb;
            g_cnt[bl] = 0u;
        }
        __syncthreads();
        unsigned int tb = sh_tb;
        for (int i = tid; i < n4; i += 1024) {
            float4 v = p[i];
            unsigned int fi = 4u * (unsigned int)i;
            float vv[4] = {v.x, v.y, v.z, v.w};
#pragma unroll
            for (int c = 0; c < 4; c++) {
                unsigned int bits = __float_as_uint(vv[c]);
                if (bits >= tb) {
                    unsigned int pos = atomicAdd(&g_cnt[bl], 1u);
                    if (pos < CAP)
                        g_cand[bl][pos] = ((unsigned long long)bits << 32)
                                        | (unsigned int)(~(fi + (unsigned int)c));
                }
            }
        }
        __syncthreads();
        cnt = g_cnt[bl];
    }

    int m = (cnt > (unsigned int)CAP) ? CAP : (int)cnt;
    int nsort;

    if (m <= 2048) {
        for (int i = tid; i < 2048; i += 1024)
            s[SPAD(i)] = (i < m) ? g_cand[bl][i] : 0ull;
        nsort = 2048;
    } else {
        // ---- exact top-(<=2048) selection by value-bin histogram ----
        int shift = c_shift[layer];
        if (tid < 1024) sh_hist[tid] = 0u;
        __syncthreads();
        for (int i = tid; i < m; i += 1024)
            atomicAdd(&sh_hist[sel_bin(g_cand[bl][i], shift)], 1u);
        __syncthreads();
        // warp-shuffle exclusive scan over 1024 bins (thread tid owns bin tid)
        unsigned int vcnt = sh_hist[tid];
        unsigned int incl = vcnt;
#pragma unroll
        for (int off = 1; off < 32; off <<= 1) {
            unsigned int t = __shfl_up_sync(0xffffffffu, incl, off);
            if (lane >= off) incl += t;
        }
        if (lane == 31) sh_wscan[warp] = incl;
        __syncthreads();
        if (tid < 32) {
            unsigned int w = sh_wscan[tid];
#pragma unroll
            for (int off = 1; off < 32; off <<= 1) {
                unsigned int t = __shfl_up_sync(0xffffffffu, w, off);
                if (lane >= off) w += t;
            }
            sh_wscan[tid] = w;
        }
        __syncthreads();
        unsigned int excl = incl - vcnt + (warp ? sh_wscan[warp - 1] : 0u);
        unsigned int cum = excl + vcnt;
        if (excl < (unsigned int)K && cum >= (unsigned int)K) {
            sh_cut = (unsigned int)tid;
            sh_total = cum;
        }
        if (tid == 0) sh_scnt = 0u;
        __syncthreads();

        if (sh_total <= 2048u) {
            unsigned int cut = sh_cut;
            for (int i = tid; i < m; i += 1024) {
                unsigned long long key = g_cand[bl][i];
                if (sel_bin(key, shift) <= cut) {
                    unsigned int pos = atomicAdd(&sh_scnt, 1u);
                    s[SPAD(pos)] = key;
                }
            }
            __syncthreads();
            unsigned int tot = sh_scnt;
            for (unsigned int i = tot + tid; i < 2048u; i += 1024u) s[SPAD(i)] = 0ull;
            nsort = 2048;
        } else {
            for (int i = tid; i < CAP; i += 1024)
                s[SPAD(i)] = (i < m) ? g_cand[bl][i] : 0ull;
            nsort = CAP;
        }
    }
    __syncthreads();

    bitonic_desc_opt<1024>(s, nsort, tid);
    // s[0..K-1] = exact sorted top-K: value desc, index asc on ties.

    const float* tlp = tl + (size_t)b * 2 * hw;
    const float* brp = br + (size_t)b * 2 * hw;
    int Wm1 = (1 << logW) - 1;

    float sc_[2], d1[2], d2[2], d3[2], d4[2];
    int flag[2];
    int tsum = 0;
#pragma unroll
    for (int u = 0; u < 2; u++) {
        int r = tid * 2 + u;
        flag[u] = 0;
        if (r < K) {
            unsigned long long key = s[SPAD(r)];
            unsigned int bits = (unsigned int)(key >> 32);
            unsigned int idx  = ~(unsigned int)key;
            int sp = (int)(idx & (unsigned int)(hw - 1));
            float fy = (float)(sp >> logW);
            float fx = (float)(sp & Wm1);
            float tx = tlp[sp], ty = tlp[hw + sp];
            float bx = brp[sp], by = brp[hw + sp];
            float tlx = fx - fmaf(1.5f, tx, 2.25f);
            float tly = fy - fmaf(1.5f, ty, 2.25f);
            float brx = fx + fmaf(1.5f, bx, 2.25f);
            float bry = fy + fmaf(1.5f, by, 2.25f);
            bool valid = !((brx < tlx) || (bry < tly));
            flag[u] = valid ? 1 : 0;
            sc_[u] = valid ? __uint_as_float(bits) : -1.0f;
            d1[u] = tlx * scale; d2[u] = tly * scale;
            d3[u] = brx * scale; d4[u] = bry * scale;
            tsum += flag[u];
        }
    }

    // block exclusive scan of valid flags (thread t owns ranks 2t, 2t+1)
    int incl2 = tsum;
#pragma unroll
    for (int off = 1; off < 32; off <<= 1) {
        int t2 = __shfl_up_sync(0xffffffffu, incl2, off);
        if (lane >= off) incl2 += t2;
    }
    if (lane == 31) wsum[warp] = incl2;
    __syncthreads();
    if (tid < 32) {
        int v = wsum[tid];
#pragma unroll
        for (int off = 1; off < 32; off <<= 1) {
            int t2 = __shfl_up_sync(0xffffffffu, v, off);
            if (lane >= off) v += t2;
        }
        wsum[tid] = v;
        if (tid == 31) wtot = v;
    }
    __syncthreads();

    int total_valid = wtot;
    int run = (warp ? wsum[warp - 1] : 0) + (incl2 - tsum);
#pragma unroll
    for (int u = 0; u < 2; u++) {
        int r = tid * 2 + u;
        if (r < K) {
            int pos = flag[u] ? run : (total_valid + (r - run));
            if (pos < ND) {
                float* d = g_det[b][layer][pos];
                d[0] = sc_[u]; d[1] = d1[u]; d[2] = d2[u];
                d[3] = d3[u];  d[4] = d4[u]; d[5] = 0.0f; d[6] = 0.0f;
            }
            run += flag[u];
        }
    }
    __syncthreads();
    if (tid < 7) g_det[b][layer][6][tid] = (float)layer;   // det.at[:,6,:] = layer
    if (tid == 0) g_cnt[bl] = 0u;                          // reset for next replay
    __syncthreads();

    // ---------------- fused final merge: third arriver of batch b does it -------------
    __threadfence();                                       // release g_det writes
    if (tid == 0) {
        unsigned int prev = atomicAdd(&g_batch[b], 1u);
        sh_last = (prev == 2u);
    }
    __syncthreads();
    if (!sh_last) return;
    __threadfence();                                       // acquire peers' g_det writes

    // build keys (reuse s unpadded: 4608 slots >= 3000)
    for (int i = tid; i < NALL; i += 1024) {
        int l = i / ND, r = i - l * ND;
        unsigned int sb = __float_as_uint(g_det[b][l][r][0]);
        unsigned int mp = (sb & 0x80000000u) ? ~sb : (sb | 0x80000000u);  // monotone map
        s[i] = ((unsigned long long)mp << 32) | (unsigned int)(~(unsigned int)i);
    }
    __syncthreads();
    if (tid < NL) ovk[tid] = s[tid * ND + 6];
    __syncthreads();

    for (int e = tid; e < NALL; e += 1024) {
        unsigned long long my = s[e];
        int rank = 0;
#pragma unroll
        for (int l = 0; l < NL; l++) {
            int lo = 0, hi = ND - 1;
            int base = l * ND;
            while (lo < hi) {
                int mid = (lo + hi) >> 1;
                int ph = mid + (mid >= 6);
                if (s[base + ph] > my) lo = mid + 1; else hi = mid;
            }
            rank += lo + (ovk[l] > my ? 1 : 0);
        }
        if (rank < ND) {
            int l = e / ND, r = e - l * ND;
            const float* src = g_det[b][l][r];
            float* dst = out + ((size_t)b * ND + rank) * 7;
#pragma unroll
            for (int c = 0; c < 7; c++) dst[c] = src[c];
        }
    }
    __syncthreads();
    if (tid == 0) g_batch[b] = 0u;                        // reset for next replay
}

extern "C" void kernel_launch(void* const* d_in, const int* in_sizes, int n_in,
                              void* d_out, int out_size) {
    const int hw[3] = {16384, 4096, 1024};

    // Resolve inputs BY SIZE (metadata order is heat0, tl0, br0, heat1, ...).
    const float* heat[3] = {0, 0, 0};
    const float* tl[3]   = {0, 0, 0};
    const float* br[3]   = {0, 0, 0};
    for (int i = 0; i < n_in; i++) {
        long long sz = in_sizes[i];
        for (int l = 0; l < 3; l++) {
            if (sz == (long long)BATCH * 80 * hw[l]) {
                heat[l] = (const float*)d_in[i];
            } else if (sz == (long long)BATCH * 2 * hw[l]) {
                if (!tl[l]) tl[l] = (const float*)d_in[i];
                else        br[l] = (const float*)d_in[i];
            }
        }
    }

    collectA_kernel<<<BLKALL, 256>>>(heat[0], heat[1], heat[2]);
    sortdet_kernel<<<NBL, 1024>>>(heat[0], heat[1], heat[2],
                                  tl[0], br[0], tl[1], br[1], tl[2], br[2],
                                  (float*)d_out);
}